// round 1
// baseline (speedup 1.0000x reference)
#include <cuda_runtime.h>
#include <cuda_fp16.h>
#include <math.h>
#include <stdint.h>

#define BB 2
#define SS 2048
#define HH 16
#define DD 128
#define HID (HH*DD)
#define SM_SCALE 0.08838834764831845f  /* 1/sqrt(128), f32-rounded from double */

// ---------------- scratch (no allocation allowed) ----------------
__device__ __half g_q16[(size_t)BB*HH*SS*DD];
__device__ __half g_k16[(size_t)BB*HH*SS*DD];
__device__ __half g_v16[(size_t)BB*HH*SS*DD];
__device__ float  g_qscale[BB*HH*(SS/32)];
__device__ float  g_kscale[BB*HH*(SS/64)];
__device__ float  g_kmean[BB*HH*DD];
__device__ float  g_vmean[BB*HH*DD];
__device__ float  g_kpart[BB*HH*16*DD];
__device__ float  g_vpart[BB*HH*16*DD];

// ---------------- means: k_mean, v_mean over seq axis ----------------
__global__ void mean_partial_kernel(const float* __restrict__ k, const float* __restrict__ v){
  int ch = blockIdx.x, bh = blockIdx.y, t = threadIdx.x;   // t = channel d
  int b = bh >> 4, h = bh & 15;
  size_t base = ((size_t)b*SS + (size_t)ch*128)*HID + h*DD + t;
  float ka = 0.f, va = 0.f;
  #pragma unroll 4
  for (int r = 0; r < 128; r++){
    ka += k[base + (size_t)r*HID];
    va += v[base + (size_t)r*HID];
  }
  g_kpart[(bh*16+ch)*DD + t] = ka;
  g_vpart[(bh*16+ch)*DD + t] = va;
}

__global__ void mean_final_kernel(){
  int bh = blockIdx.x, t = threadIdx.x;
  float ka = 0.f, va = 0.f;
  #pragma unroll
  for (int c = 0; c < 16; c++){
    ka += g_kpart[(bh*16+c)*DD + t];
    va += g_vpart[(bh*16+c)*DD + t];
  }
  g_kmean[bh*DD + t] = ka / (float)SS;
  g_vmean[bh*DD + t] = va / (float)SS;
}

// ---------------- block max helper ----------------
__device__ __forceinline__ float block_absmax(float v, float* red){
  #pragma unroll
  for (int o = 16; o > 0; o >>= 1)
    v = fmaxf(v, __shfl_xor_sync(0xffffffffu, v, o));
  int w = threadIdx.x >> 5;
  if ((threadIdx.x & 31) == 0) red[w] = v;
  __syncthreads();
  float r = red[0];
  #pragma unroll
  for (int i = 1; i < 8; i++) r = fmaxf(r, red[i]);
  return r;
}

// ---------------- quantize Q (groups of 32 rows) ----------------
__global__ void quant_q_kernel(const float* __restrict__ q){
  __shared__ float red[8];
  int blk = blockIdx.x;              // bh*64 + g
  int g = blk & 63, bh = blk >> 6;
  int b = bh >> 4, h = bh & 15;
  int t = threadIdx.x;
  float vals[16]; float amax = 0.f;
  size_t inbase = ((size_t)b*SS + (size_t)g*32)*HID + h*DD;
  #pragma unroll
  for (int i = 0; i < 16; i++){
    int idx = t + i*256;
    int r = idx >> 7, d = idx & 127;
    float x = q[inbase + (size_t)r*HID + d];
    vals[i] = x; amax = fmaxf(amax, fabsf(x));
  }
  amax = block_absmax(amax, red);
  float scale = fmaxf(amax / 127.0f, 1e-8f);
  size_t obase = ((size_t)bh*SS + (size_t)g*32)*DD;
  #pragma unroll
  for (int i = 0; i < 16; i++){
    int idx = t + i*256;
    int r = idx >> 7, d = idx & 127;
    float xq = rintf(vals[i] / scale);
    xq = fminf(fmaxf(xq, -127.f), 127.f);
    g_q16[obase + (size_t)r*DD + d] = __float2half_rn(xq);
  }
  if (t == 0) g_qscale[blk] = scale;
}

// ---------------- quantize smoothed K (groups of 64 rows) ----------------
__global__ void quant_k_kernel(const float* __restrict__ k){
  __shared__ float red[8];
  int blk = blockIdx.x;              // bh*32 + g
  int g = blk & 31, bh = blk >> 5;
  int b = bh >> 4, h = bh & 15;
  int t = threadIdx.x;
  float vals[32]; float amax = 0.f;
  size_t inbase = ((size_t)b*SS + (size_t)g*64)*HID + h*DD;
  #pragma unroll
  for (int i = 0; i < 32; i++){
    int idx = t + i*256;
    int r = idx >> 7, d = idx & 127;
    float x = k[inbase + (size_t)r*HID + d] - g_kmean[bh*DD + d];
    vals[i] = x; amax = fmaxf(amax, fabsf(x));
  }
  amax = block_absmax(amax, red);
  float scale = fmaxf(amax / 127.0f, 1e-8f);
  size_t obase = ((size_t)bh*SS + (size_t)g*64)*DD;
  #pragma unroll
  for (int i = 0; i < 32; i++){
    int idx = t + i*256;
    int r = idx >> 7, d = idx & 127;
    float xq = rintf(vals[i] / scale);
    xq = fminf(fmaxf(xq, -127.f), 127.f);
    g_k16[obase + (size_t)r*DD + d] = __float2half_rn(xq);
  }
  if (t == 0) g_kscale[blk] = scale;
}

// ---------------- smoothed V -> f16 ----------------
__global__ void smooth_v_kernel(const float* __restrict__ v){
  size_t tid = (size_t)blockIdx.x*256 + threadIdx.x;  // 2097152 threads
  #pragma unroll
  for (int i = 0; i < 4; i++){
    size_t idx = tid + (size_t)i*2097152;
    int d  = (int)(idx & 127);
    int s  = (int)((idx >> 7) & (SS-1));
    int bh = (int)(idx >> 18);
    int b = bh >> 4, h = bh & 15;
    float x = v[((size_t)b*SS + s)*HID + h*DD + d] - g_vmean[bh*DD + d];
    g_v16[idx] = __float2half_rn(x);
  }
}

// ---------------- mma.sync m16n8k16 f16 -> f32 ----------------
__device__ __forceinline__ void mma16816(float c[4], const uint32_t a[4], uint32_t b0, uint32_t b1){
  asm volatile(
    "mma.sync.aligned.m16n8k16.row.col.f32.f16.f16.f32 "
    "{%0,%1,%2,%3}, {%4,%5,%6,%7}, {%8,%9}, {%0,%1,%2,%3};\n"
    : "+f"(c[0]), "+f"(c[1]), "+f"(c[2]), "+f"(c[3])
    : "r"(a[0]), "r"(a[1]), "r"(a[2]), "r"(a[3]), "r"(b0), "r"(b1));
}

// ---------------- main attention kernel ----------------
__global__ void __launch_bounds__(128)
attn_kernel(const int* __restrict__ wlp, const int* __restrict__ wrp, float* __restrict__ out){
  __shared__ __half sQK[64][136];   // Q staging, then K tile (padded rows)
  __shared__ __half sVt[128][72];   // V tile transposed [d][key] (padded)

  const int i0  = blockIdx.x * 64;
  const int bh  = blockIdx.y;
  const int b   = bh >> 4, h = bh & 15;
  const int tid = threadIdx.x, wid = tid >> 5, lane = tid & 31;
  const int r   = lane >> 2, q2 = (lane & 3) * 2;
  const int wl = *wlp, wr = *wrp;

  // --- load Q tile, build register A-fragments ---
  const __half* Qg = g_q16 + ((size_t)bh*SS + i0)*DD;
  #pragma unroll
  for (int it = tid; it < 1024; it += 128){
    int row = it >> 4, c8 = (it & 15) << 3;
    *(uint4*)&sQK[row][c8] = *(const uint4*)(Qg + (size_t)row*DD + c8);
  }
  __syncthreads();
  const int qrow = wid*16 + r;
  uint32_t afrag[8][4];
  #pragma unroll
  for (int kc = 0; kc < 8; kc++){
    afrag[kc][0] = *(const uint32_t*)&sQK[qrow  ][kc*16 + q2    ];
    afrag[kc][1] = *(const uint32_t*)&sQK[qrow+8][kc*16 + q2    ];
    afrag[kc][2] = *(const uint32_t*)&sQK[qrow  ][kc*16 + q2 + 8];
    afrag[kc][3] = *(const uint32_t*)&sQK[qrow+8][kc*16 + q2 + 8];
  }
  __syncthreads();

  const float qs = g_qscale[bh*(SS/32) + ((i0 + wid*16) >> 5)];
  const int i_r0 = i0 + qrow, i_r1 = i_r0 + 8;
  const int lo0 = (wl < 0) ? -0x40000000 : i_r0 - wl;
  const int hi0 = (wr < 0) ?  0x40000000 : i_r0 + wr;
  const int lo1 = (wl < 0) ? -0x40000000 : i_r1 - wl;
  const int hi1 = (wr < 0) ?  0x40000000 : i_r1 + wr;

  float of[16][4];
  #pragma unroll
  for (int n = 0; n < 16; n++){ of[n][0]=0.f; of[n][1]=0.f; of[n][2]=0.f; of[n][3]=0.f; }
  float m0 = -1e30f, m1 = -1e30f, l0 = 0.f, l1 = 0.f;

  int jlo = (wl >= 0) ? max(0, i0 - wl) : 0;
  int jhi = (wr >= 0) ? min(SS-1, i0 + 63 + wr) : SS-1;

  for (int j0 = jlo & ~63; j0 <= jhi; j0 += 64){
    // --- load K tile and V tile (transposed) ---
    const __half* Kg = g_k16 + ((size_t)bh*SS + j0)*DD;
    #pragma unroll
    for (int it = tid; it < 1024; it += 128){
      int row = it >> 4, c8 = (it & 15) << 3;
      *(uint4*)&sQK[row][c8] = *(const uint4*)(Kg + (size_t)row*DD + c8);
    }
    const __half* Vg = g_v16 + ((size_t)bh*SS + j0)*DD;
    #pragma unroll
    for (int it = tid; it < 1024; it += 128){
      int row = it >> 4, c8 = (it & 15) << 3;
      uint4 u = *(const uint4*)(Vg + (size_t)row*DD + c8);
      __half hv[8]; *(uint4*)hv = u;
      #pragma unroll
      for (int jj = 0; jj < 8; jj++) sVt[c8+jj][row] = hv[jj];
    }
    __syncthreads();

    // --- S = Q K^T (exact integer math in f32 accumulators) ---
    float sf[8][4];
    #pragma unroll
    for (int n = 0; n < 8; n++){ sf[n][0]=0.f; sf[n][1]=0.f; sf[n][2]=0.f; sf[n][3]=0.f; }
    #pragma unroll
    for (int kc = 0; kc < 8; kc++){
      #pragma unroll
      for (int nf = 0; nf < 8; nf++){
        uint32_t b0 = *(const uint32_t*)&sQK[nf*8 + r][kc*16 + q2    ];
        uint32_t b1 = *(const uint32_t*)&sQK[nf*8 + r][kc*16 + q2 + 8];
        mma16816(sf[nf], afrag[kc], b0, b1);
      }
    }

    // --- dequant + sliding-window mask ---
    const float ks = g_kscale[bh*(SS/64) + (j0 >> 6)];
    float mt0 = -INFINITY, mt1 = -INFINITY;
    #pragma unroll
    for (int nf = 0; nf < 8; nf++){
      int jc = j0 + nf*8 + q2;
      float s00 = (jc   >= lo0 && jc   <= hi0) ? ((sf[nf][0]*qs)*ks)*SM_SCALE : -INFINITY;
      float s01 = (jc+1 >= lo0 && jc+1 <= hi0) ? ((sf[nf][1]*qs)*ks)*SM_SCALE : -INFINITY;
      float s10 = (jc   >= lo1 && jc   <= hi1) ? ((sf[nf][2]*qs)*ks)*SM_SCALE : -INFINITY;
      float s11 = (jc+1 >= lo1 && jc+1 <= hi1) ? ((sf[nf][3]*qs)*ks)*SM_SCALE : -INFINITY;
      sf[nf][0]=s00; sf[nf][1]=s01; sf[nf][2]=s10; sf[nf][3]=s11;
      mt0 = fmaxf(mt0, fmaxf(s00, s01));
      mt1 = fmaxf(mt1, fmaxf(s10, s11));
    }
    mt0 = fmaxf(mt0, __shfl_xor_sync(0xffffffffu, mt0, 1));
    mt0 = fmaxf(mt0, __shfl_xor_sync(0xffffffffu, mt0, 2));
    mt1 = fmaxf(mt1, __shfl_xor_sync(0xffffffffu, mt1, 1));
    mt1 = fmaxf(mt1, __shfl_xor_sync(0xffffffffu, mt1, 2));

    float mn0 = fmaxf(m0, mt0), mn1 = fmaxf(m1, mt1);
    float a0 = __expf(m0 - mn0), a1 = __expf(m1 - mn1);
    float t0 = 0.f, t1 = 0.f;
    #pragma unroll
    for (int nf = 0; nf < 8; nf++){
      float e00 = __expf(sf[nf][0] - mn0);
      float e01 = __expf(sf[nf][1] - mn0);
      float e10 = __expf(sf[nf][2] - mn1);
      float e11 = __expf(sf[nf][3] - mn1);
      sf[nf][0]=e00; sf[nf][1]=e01; sf[nf][2]=e10; sf[nf][3]=e11;
      t0 += e00 + e01; t1 += e10 + e11;
    }
    t0 += __shfl_xor_sync(0xffffffffu, t0, 1);
    t0 += __shfl_xor_sync(0xffffffffu, t0, 2);
    t1 += __shfl_xor_sync(0xffffffffu, t1, 1);
    t1 += __shfl_xor_sync(0xffffffffu, t1, 2);
    l0 = l0*a0 + t0; l1 = l1*a1 + t1;
    m0 = mn0; m1 = mn1;
    #pragma unroll
    for (int n = 0; n < 16; n++){
      of[n][0]*=a0; of[n][1]*=a0; of[n][2]*=a1; of[n][3]*=a1;
    }

    // --- pack P to f16 A-fragments (matches reference f16 rounding) ---
    uint32_t pfrag[4][4];
    #pragma unroll
    for (int kc = 0; kc < 4; kc++){
      __half2 p0 = __floats2half2_rn(sf[2*kc  ][0], sf[2*kc  ][1]);
      __half2 p1 = __floats2half2_rn(sf[2*kc  ][2], sf[2*kc  ][3]);
      __half2 p2 = __floats2half2_rn(sf[2*kc+1][0], sf[2*kc+1][1]);
      __half2 p3 = __floats2half2_rn(sf[2*kc+1][2], sf[2*kc+1][3]);
      pfrag[kc][0] = *(uint32_t*)&p0; pfrag[kc][1] = *(uint32_t*)&p1;
      pfrag[kc][2] = *(uint32_t*)&p2; pfrag[kc][3] = *(uint32_t*)&p3;
    }

    // --- O += P V ---
    #pragma unroll
    for (int n = 0; n < 16; n++){
      #pragma unroll
      for (int kc = 0; kc < 4; kc++){
        uint32_t b0 = *(const uint32_t*)&sVt[n*8 + r][kc*16 + q2    ];
        uint32_t b1 = *(const uint32_t*)&sVt[n*8 + r][kc*16 + q2 + 8];
        mma16816(of[n], pfrag[kc], b0, b1);
      }
    }
    __syncthreads();
  }

  // --- epilogue: normalize, f16-round (ref out16), add v_mean ---
  float inv0 = 1.0f / l0, inv1 = 1.0f / l1;
  float* ob = out + ((size_t)b*SS)*HID + h*DD;
  const float* vm = g_vmean + bh*DD;
  #pragma unroll
  for (int n = 0; n < 16; n++){
    int d0 = n*8 + q2;
    float2 o0, o1;
    o0.x = __half2float(__float2half_rn(of[n][0]*inv0)) + vm[d0];
    o0.y = __half2float(__float2half_rn(of[n][1]*inv0)) + vm[d0+1];
    o1.x = __half2float(__float2half_rn(of[n][2]*inv1)) + vm[d0];
    o1.y = __half2float(__float2half_rn(of[n][3]*inv1)) + vm[d0+1];
    *(float2*)(ob + (size_t)i_r0*HID + d0) = o0;
    *(float2*)(ob + (size_t)i_r1*HID + d0) = o1;
  }
}

// ---------------- launch ----------------
extern "C" void kernel_launch(void* const* d_in, const int* in_sizes, int n_in,
                              void* d_out, int out_size){
  const float* q = (const float*)d_in[0];
  const float* k = (const float*)d_in[1];
  const float* v = (const float*)d_in[2];
  const int* wl  = (const int*)d_in[3];
  const int* wr  = (const int*)d_in[4];
  float* out = (float*)d_out;

  mean_partial_kernel<<<dim3(16, BB*HH), 128>>>(k, v);
  mean_final_kernel<<<BB*HH, 128>>>();
  quant_q_kernel<<<BB*HH*(SS/32), 256>>>(q);
  quant_k_kernel<<<BB*HH*(SS/64), 256>>>(k);
  smooth_v_kernel<<<8192, 256>>>(v);
  attn_kernel<<<dim3(SS/64, BB*HH), 128>>>(wl, wr, out);
}

// round 2
// speedup vs baseline: 1.6991x; 1.6991x over previous
#include <cuda_runtime.h>
#include <cuda_fp16.h>
#include <math.h>
#include <stdint.h>

#define BB 2
#define SS 2048
#define HH 16
#define DD 128
#define HID (HH*DD)
#define SM_SCALE 0.08838834764831845f  /* 1/sqrt(128) */

// ---------------- scratch (no allocation allowed) ----------------
__device__ signed char g_q8[(size_t)BB*HH*SS*DD];
__device__ signed char g_k8[(size_t)BB*HH*SS*DD];
__device__ __half      g_v16[(size_t)BB*HH*SS*DD];
__device__ float g_qscale[BB*HH*(SS/32)];
__device__ float g_kscale[BB*HH*(SS/64)];
__device__ float g_kmean[BB*HH*DD];
__device__ float g_vmean[BB*HH*DD];
__device__ float g_kpart[BB*HH*16*DD];
__device__ float g_vpart[BB*HH*16*DD];

// ---------------- means over seq axis ----------------
__global__ void mean_partial_kernel(const float* __restrict__ k, const float* __restrict__ v){
  int ch = blockIdx.x, bh = blockIdx.y, t = threadIdx.x;
  int b = bh >> 4, h = bh & 15;
  size_t base = ((size_t)b*SS + (size_t)ch*128)*HID + h*DD + t;
  float ka = 0.f, va = 0.f;
  #pragma unroll 4
  for (int r = 0; r < 128; r++){
    ka += k[base + (size_t)r*HID];
    va += v[base + (size_t)r*HID];
  }
  g_kpart[(bh*16+ch)*DD + t] = ka;
  g_vpart[(bh*16+ch)*DD + t] = va;
}

__global__ void mean_final_kernel(){
  int bh = blockIdx.x, t = threadIdx.x;
  float ka = 0.f, va = 0.f;
  #pragma unroll
  for (int c = 0; c < 16; c++){
    ka += g_kpart[(bh*16+c)*DD + t];
    va += g_vpart[(bh*16+c)*DD + t];
  }
  g_kmean[bh*DD + t] = ka / (float)SS;
  g_vmean[bh*DD + t] = va / (float)SS;
}

// ---------------- block absmax ----------------
__device__ __forceinline__ float block_absmax(float v, float* red){
  #pragma unroll
  for (int o = 16; o > 0; o >>= 1)
    v = fmaxf(v, __shfl_xor_sync(0xffffffffu, v, o));
  int w = threadIdx.x >> 5;
  if ((threadIdx.x & 31) == 0) red[w] = v;
  __syncthreads();
  float r = red[0];
  #pragma unroll
  for (int i = 1; i < 8; i++) r = fmaxf(r, red[i]);
  return r;
}

// ---------------- quantize Q (32-row groups) -> int8 ----------------
__global__ void quant_q_kernel(const float* __restrict__ q){
  __shared__ float red[8];
  int blk = blockIdx.x;              // bh*64 + g
  int g = blk & 63, bh = blk >> 6;
  int b = bh >> 4, h = bh & 15;
  int t = threadIdx.x;
  float vals[16]; float amax = 0.f;
  size_t inbase = ((size_t)b*SS + (size_t)g*32)*HID + h*DD;
  #pragma unroll
  for (int i = 0; i < 16; i++){
    int idx = t + i*256;
    int r = idx >> 7, d = idx & 127;
    float x = q[inbase + (size_t)r*HID + d];
    vals[i] = x; amax = fmaxf(amax, fabsf(x));
  }
  amax = block_absmax(amax, red);
  float scale = fmaxf(amax / 127.0f, 1e-8f);
  size_t obase = ((size_t)bh*SS + (size_t)g*32)*DD;
  #pragma unroll
  for (int i = 0; i < 16; i++){
    int idx = t + i*256;
    int r = idx >> 7, d = idx & 127;
    float xq = rintf(vals[i] / scale);
    xq = fminf(fmaxf(xq, -127.f), 127.f);
    g_q8[obase + (size_t)r*DD + d] = (signed char)(int)xq;
  }
  if (t == 0) g_qscale[blk] = scale;
}

// ---------------- quantize smoothed K (64-row groups) -> int8 ----------------
__global__ void quant_k_kernel(const float* __restrict__ k){
  __shared__ float red[8];
  int blk = blockIdx.x;              // bh*32 + g
  int g = blk & 31, bh = blk >> 5;
  int b = bh >> 4, h = bh & 15;
  int t = threadIdx.x;
  float vals[32]; float amax = 0.f;
  size_t inbase = ((size_t)b*SS + (size_t)g*64)*HID + h*DD;
  #pragma unroll
  for (int i = 0; i < 32; i++){
    int idx = t + i*256;
    int r = idx >> 7, d = idx & 127;
    float x = k[inbase + (size_t)r*HID + d] - g_kmean[bh*DD + d];
    vals[i] = x; amax = fmaxf(amax, fabsf(x));
  }
  amax = block_absmax(amax, red);
  float scale = fmaxf(amax / 127.0f, 1e-8f);
  size_t obase = ((size_t)bh*SS + (size_t)g*64)*DD;
  #pragma unroll
  for (int i = 0; i < 32; i++){
    int idx = t + i*256;
    int r = idx >> 7, d = idx & 127;
    float xq = rintf(vals[i] / scale);
    xq = fminf(fmaxf(xq, -127.f), 127.f);
    g_k8[obase + (size_t)r*DD + d] = (signed char)(int)xq;
  }
  if (t == 0) g_kscale[blk] = scale;
}

// ---------------- smoothed V -> f16 ----------------
__global__ void smooth_v_kernel(const float* __restrict__ v){
  size_t tid = (size_t)blockIdx.x*256 + threadIdx.x;
  #pragma unroll
  for (int i = 0; i < 4; i++){
    size_t idx = tid + (size_t)i*2097152;
    int d  = (int)(idx & 127);
    int s  = (int)((idx >> 7) & (SS-1));
    int bh = (int)(idx >> 18);
    int b = bh >> 4, h = bh & 15;
    float x = v[((size_t)b*SS + s)*HID + h*DD + d] - g_vmean[bh*DD + d];
    g_v16[idx] = __float2half_rn(x);
  }
}

// ---------------- MMA helpers ----------------
__device__ __forceinline__ void mma16816(float c[4], const uint32_t a[4], uint32_t b0, uint32_t b1){
  asm volatile(
    "mma.sync.aligned.m16n8k16.row.col.f32.f16.f16.f32 "
    "{%0,%1,%2,%3}, {%4,%5,%6,%7}, {%8,%9}, {%0,%1,%2,%3};\n"
    : "+f"(c[0]), "+f"(c[1]), "+f"(c[2]), "+f"(c[3])
    : "r"(a[0]), "r"(a[1]), "r"(a[2]), "r"(a[3]), "r"(b0), "r"(b1));
}
__device__ __forceinline__ void mma_s8(int c[4], const uint32_t a[4], uint32_t b0, uint32_t b1){
  asm volatile(
    "mma.sync.aligned.m16n8k32.row.col.s32.s8.s8.s32 "
    "{%0,%1,%2,%3}, {%4,%5,%6,%7}, {%8,%9}, {%0,%1,%2,%3};\n"
    : "+r"(c[0]), "+r"(c[1]), "+r"(c[2]), "+r"(c[3])
    : "r"(a[0]), "r"(a[1]), "r"(a[2]), "r"(a[3]), "r"(b0), "r"(b1));
}
__device__ __forceinline__ void ldmx4t(uint32_t& t0, uint32_t& t1, uint32_t& t2, uint32_t& t3, uint32_t addr){
  asm volatile("ldmatrix.sync.aligned.m8n8.x4.trans.shared.b16 {%0,%1,%2,%3}, [%4];\n"
    : "=r"(t0), "=r"(t1), "=r"(t2), "=r"(t3) : "r"(addr));
}
#define CP16(dst, src) asm volatile("cp.async.cg.shared.global [%0], [%1], 16;\n" :: "r"(dst), "l"(src) : "memory")

// smem layout (dynamic): K stages 2x 64x144 int8, V stages 2x 64x272 bytes
#define KPITCH 144
#define VPITCH 272
#define SK_OFF(st) ((st)*64*KPITCH)
#define SV_OFF(st) (2*64*KPITCH + (st)*64*VPITCH)
#define SMEM_TOTAL (2*64*KPITCH + 2*64*VPITCH)   // 53248

// ---------------- main attention kernel ----------------
__global__ void __launch_bounds__(128)
attn_kernel(const int* __restrict__ wlp, const int* __restrict__ wrp, float* __restrict__ out){
  extern __shared__ char smem[];
  const uint32_t smem_b = (uint32_t)__cvta_generic_to_shared(smem);

  const int i0  = blockIdx.x * 64;
  const int bh  = blockIdx.y;
  const int b   = bh >> 4, h = bh & 15;
  const int tid = threadIdx.x, wid = tid >> 5, lane = tid & 31;
  const int r   = lane >> 2, q2 = (lane & 3) * 2, c4 = (lane & 3) * 4;
  const int wl = *wlp, wr = *wrp;

  const signed char* Qg = g_q8 + ((size_t)bh*SS + i0)*DD;
  const signed char* Kg = g_k8 + (size_t)bh*SS*DD;
  const __half*      Vg = g_v16 + (size_t)bh*SS*DD;

  // --- stage Q into sK[0] region, build int8 A-fragments ---
  {
    char* sQ = smem;  // rows of 128B at pitch KPITCH
    #pragma unroll
    for (int it = tid; it < 512; it += 128){
      int row = it >> 3, seg = it & 7;
      *(uint4*)(sQ + row*KPITCH + seg*16) = *(const uint4*)(Qg + row*128 + seg*16);
    }
  }
  __syncthreads();
  const int qrow = wid*16 + r;
  uint32_t afrag[4][4];
  #pragma unroll
  for (int kc = 0; kc < 4; kc++){
    const char* sQ = smem;
    afrag[kc][0] = *(const uint32_t*)(sQ + (qrow  )*KPITCH + kc*32 + c4     );
    afrag[kc][1] = *(const uint32_t*)(sQ + (qrow+8)*KPITCH + kc*32 + c4     );
    afrag[kc][2] = *(const uint32_t*)(sQ + (qrow  )*KPITCH + kc*32 + c4 + 16);
    afrag[kc][3] = *(const uint32_t*)(sQ + (qrow+8)*KPITCH + kc*32 + c4 + 16);
  }
  __syncthreads();

  const float qs = g_qscale[bh*(SS/32) + ((i0 + wid*16) >> 5)];
  const int i_r0 = i0 + qrow, i_r1 = i_r0 + 8;
  const int lo0 = (wl < 0) ? -0x40000000 : i_r0 - wl;
  const int hi0 = (wr < 0) ?  0x40000000 : i_r0 + wr;
  const int lo1 = (wl < 0) ? -0x40000000 : i_r1 - wl;
  const int hi1 = (wr < 0) ?  0x40000000 : i_r1 + wr;

  float of[16][4];
  #pragma unroll
  for (int n = 0; n < 16; n++){ of[n][0]=0.f; of[n][1]=0.f; of[n][2]=0.f; of[n][3]=0.f; }
  float m0 = -1e30f, m1 = -1e30f, l0 = 0.f, l1 = 0.f;

  int jlo = (wl >= 0) ? max(0, i0 - wl) : 0;
  int jhi = (wr >= 0) ? min(SS-1, i0 + 63 + wr) : SS-1;
  const int jloT = jlo & ~63;
  const int nt = ((jhi - jloT) >> 6) + 1;

  // issue tile loads into stage st
  auto issue = [&](int st, int j0){
    uint32_t kb = smem_b + SK_OFF(st);
    const signed char* kg = Kg + (size_t)j0*128;
    #pragma unroll
    for (int c = tid; c < 512; c += 128){
      int row = c >> 3, seg = c & 7;
      CP16(kb + row*KPITCH + seg*16, kg + row*128 + seg*16);
    }
    uint32_t vb = smem_b + SV_OFF(st);
    const __half* vg = Vg + (size_t)j0*128;
    #pragma unroll
    for (int c = tid; c < 1024; c += 128){
      int row = c >> 4, seg = c & 15;
      CP16(vb + row*VPITCH + seg*16, (const char*)vg + row*256 + seg*16);
    }
    asm volatile("cp.async.commit_group;\n" ::: "memory");
  };

  issue(0, jloT);

  for (int it = 0; it < nt; it++){
    const int j0 = jloT + it*64;
    const int st = it & 1;
    if (it + 1 < nt){
      issue(st ^ 1, j0 + 64);
      asm volatile("cp.async.wait_group 1;\n" ::: "memory");
    } else {
      asm volatile("cp.async.wait_group 0;\n" ::: "memory");
    }
    __syncthreads();

    // --- S = Q K^T (int8 MMA, exact) ---
    int acc[8][4];
    #pragma unroll
    for (int n = 0; n < 8; n++){ acc[n][0]=0; acc[n][1]=0; acc[n][2]=0; acc[n][3]=0; }
    const char* sK = smem + SK_OFF(st);
    #pragma unroll
    for (int kc = 0; kc < 4; kc++){
      #pragma unroll
      for (int nf = 0; nf < 8; nf++){
        uint32_t b0 = *(const uint32_t*)(sK + (nf*8 + r)*KPITCH + kc*32 + c4     );
        uint32_t b1 = *(const uint32_t*)(sK + (nf*8 + r)*KPITCH + kc*32 + c4 + 16);
        mma_s8(acc[nf], afrag[kc], b0, b1);
      }
    }

    // --- dequant + sliding-window mask ---
    const float ks = g_kscale[bh*(SS/64) + (j0 >> 6)];
    float sf[8][4];
    float mt0 = -INFINITY, mt1 = -INFINITY;
    #pragma unroll
    for (int nf = 0; nf < 8; nf++){
      int jc = j0 + nf*8 + q2;
      float f0 = __int2float_rn(acc[nf][0]);
      float f1 = __int2float_rn(acc[nf][1]);
      float f2 = __int2float_rn(acc[nf][2]);
      float f3 = __int2float_rn(acc[nf][3]);
      float s00 = (jc   >= lo0 && jc   <= hi0) ? ((f0*qs)*ks)*SM_SCALE : -INFINITY;
      float s01 = (jc+1 >= lo0 && jc+1 <= hi0) ? ((f1*qs)*ks)*SM_SCALE : -INFINITY;
      float s10 = (jc   >= lo1 && jc   <= hi1) ? ((f2*qs)*ks)*SM_SCALE : -INFINITY;
      float s11 = (jc+1 >= lo1 && jc+1 <= hi1) ? ((f3*qs)*ks)*SM_SCALE : -INFINITY;
      sf[nf][0]=s00; sf[nf][1]=s01; sf[nf][2]=s10; sf[nf][3]=s11;
      mt0 = fmaxf(mt0, fmaxf(s00, s01));
      mt1 = fmaxf(mt1, fmaxf(s10, s11));
    }
    mt0 = fmaxf(mt0, __shfl_xor_sync(0xffffffffu, mt0, 1));
    mt0 = fmaxf(mt0, __shfl_xor_sync(0xffffffffu, mt0, 2));
    mt1 = fmaxf(mt1, __shfl_xor_sync(0xffffffffu, mt1, 1));
    mt1 = fmaxf(mt1, __shfl_xor_sync(0xffffffffu, mt1, 2));

    float mn0 = fmaxf(m0, mt0), mn1 = fmaxf(m1, mt1);
    float a0 = __expf(m0 - mn0), a1 = __expf(m1 - mn1);
    float t0 = 0.f, t1 = 0.f;
    #pragma unroll
    for (int nf = 0; nf < 8; nf++){
      float e00 = __expf(sf[nf][0] - mn0);
      float e01 = __expf(sf[nf][1] - mn0);
      float e10 = __expf(sf[nf][2] - mn1);
      float e11 = __expf(sf[nf][3] - mn1);
      sf[nf][0]=e00; sf[nf][1]=e01; sf[nf][2]=e10; sf[nf][3]=e11;
      t0 += e00 + e01; t1 += e10 + e11;
    }
    t0 += __shfl_xor_sync(0xffffffffu, t0, 1);
    t0 += __shfl_xor_sync(0xffffffffu, t0, 2);
    t1 += __shfl_xor_sync(0xffffffffu, t1, 1);
    t1 += __shfl_xor_sync(0xffffffffu, t1, 2);
    l0 = l0*a0 + t0; l1 = l1*a1 + t1;
    m0 = mn0; m1 = mn1;
    #pragma unroll
    for (int n = 0; n < 16; n++){
      of[n][0]*=a0; of[n][1]*=a0; of[n][2]*=a1; of[n][3]*=a1;
    }

    // --- pack P to f16 A-fragments ---
    uint32_t pfrag[4][4];
    #pragma unroll
    for (int kc = 0; kc < 4; kc++){
      __half2 p0 = __floats2half2_rn(sf[2*kc  ][0], sf[2*kc  ][1]);
      __half2 p1 = __floats2half2_rn(sf[2*kc  ][2], sf[2*kc  ][3]);
      __half2 p2 = __floats2half2_rn(sf[2*kc+1][0], sf[2*kc+1][1]);
      __half2 p3 = __floats2half2_rn(sf[2*kc+1][2], sf[2*kc+1][3]);
      pfrag[kc][0] = *(uint32_t*)&p0; pfrag[kc][1] = *(uint32_t*)&p1;
      pfrag[kc][2] = *(uint32_t*)&p2; pfrag[kc][3] = *(uint32_t*)&p3;
    }

    // --- O += P V : V^T fragments via ldmatrix.trans ---
    const uint32_t svb = smem_b + SV_OFF(st);
    const int jrow = lane & 15;
    const int dsel = (lane & 16) ? 8 : 0;
    #pragma unroll
    for (int jc = 0; jc < 4; jc++){
      #pragma unroll
      for (int dc = 0; dc < 8; dc++){
        uint32_t addr = svb + (jc*16 + jrow)*VPITCH + (dc*16 + dsel)*2;
        uint32_t v0, v1, v2, v3;
        ldmx4t(v0, v1, v2, v3, addr);
        mma16816(of[dc*2    ], pfrag[jc], v0, v1);
        mma16816(of[dc*2 + 1], pfrag[jc], v2, v3);
      }
    }
    __syncthreads();
  }

  // --- epilogue: normalize, f16-round, add v_mean ---
  float inv0 = 1.0f / l0, inv1 = 1.0f / l1;
  float* ob = out + ((size_t)b*SS)*HID + h*DD;
  const float* vm = g_vmean + bh*DD;
  #pragma unroll
  for (int n = 0; n < 16; n++){
    int d0 = n*8 + q2;
    float2 o0, o1;
    o0.x = __half2float(__float2half_rn(of[n][0]*inv0)) + vm[d0];
    o0.y = __half2float(__float2half_rn(of[n][1]*inv0)) + vm[d0+1];
    o1.x = __half2float(__float2half_rn(of[n][2]*inv1)) + vm[d0];
    o1.y = __half2float(__float2half_rn(of[n][3]*inv1)) + vm[d0+1];
    *(float2*)(ob + (size_t)i_r0*HID + d0) = o0;
    *(float2*)(ob + (size_t)i_r1*HID + d0) = o1;
  }
}

// ---------------- launch ----------------
extern "C" void kernel_launch(void* const* d_in, const int* in_sizes, int n_in,
                              void* d_out, int out_size){
  const float* q = (const float*)d_in[0];
  const float* k = (const float*)d_in[1];
  const float* v = (const float*)d_in[2];
  const int* wl  = (const int*)d_in[3];
  const int* wr  = (const int*)d_in[4];
  float* out = (float*)d_out;

  cudaFuncSetAttribute(attn_kernel, cudaFuncAttributeMaxDynamicSharedMemorySize, SMEM_TOTAL);

  mean_partial_kernel<<<dim3(16, BB*HH), 128>>>(k, v);
  mean_final_kernel<<<BB*HH, 128>>>();
  quant_q_kernel<<<BB*HH*(SS/32), 256>>>(q);
  quant_k_kernel<<<BB*HH*(SS/64), 256>>>(k);
  smooth_v_kernel<<<8192, 256>>>(v);
  attn_kernel<<<dim3(SS/64, BB*HH), 128, SMEM_TOTAL>>>(wl, wr, out);
}

// round 3
// speedup vs baseline: 1.8936x; 1.1145x over previous
#include <cuda_runtime.h>
#include <cuda_fp16.h>
#include <math.h>
#include <stdint.h>

#define BB 2
#define SS 2048
#define HH 16
#define DD 128
#define HID (HH*DD)
#define SM_SCALE_L2E 0.12751649736230442f   /* (1/sqrt(128)) * log2(e) */

// ---------------- scratch (no allocation allowed) ----------------
__device__ signed char g_q8[(size_t)BB*HH*SS*DD];
__device__ signed char g_k8[(size_t)BB*HH*SS*DD];
__device__ __half      g_v16[(size_t)BB*HH*SS*DD];
__device__ float g_qscale[BB*HH*(SS/32)];
__device__ float g_kscale[BB*HH*(SS/64)];
__device__ float g_kmean[BB*HH*DD];
__device__ float g_vmean[BB*HH*DD];
__device__ float g_kpart[BB*HH*32*DD];
__device__ float g_vpart[BB*HH*32*DD];

// ---------------- block absmax (256 threads / 8 warps) ----------------
__device__ __forceinline__ float block_absmax(float v, float* red){
  #pragma unroll
  for (int o = 16; o > 0; o >>= 1)
    v = fmaxf(v, __shfl_xor_sync(0xffffffffu, v, o));
  int w = threadIdx.x >> 5;
  if ((threadIdx.x & 31) == 0) red[w] = v;
  __syncthreads();
  float r = red[0];
  #pragma unroll
  for (int i = 1; i < 8; i++) r = fmaxf(r, red[i]);
  return r;
}

// ---------------- K0: mean partials (bx<16) + quant_q (bx>=16) ----------------
__global__ void __launch_bounds__(256)
pre_k0(const float* __restrict__ q, const float* __restrict__ k, const float* __restrict__ v){
  int bh = blockIdx.y, bx = blockIdx.x;
  int b = bh >> 4, h = bh & 15;
  int t = threadIdx.x;
  if (bx < 16){
    int d = t & 127, hf = t >> 7;
    size_t base = ((size_t)b*SS + (size_t)bx*128 + (size_t)hf*64)*HID + h*DD + d;
    float ka = 0.f, va = 0.f;
    #pragma unroll 4
    for (int r2 = 0; r2 < 64; r2++){
      ka += k[base + (size_t)r2*HID];
      va += v[base + (size_t)r2*HID];
    }
    g_kpart[((bh*16 + bx)*2 + hf)*DD + d] = ka;
    g_vpart[((bh*16 + bx)*2 + hf)*DD + d] = va;
  } else {
    __shared__ float red[8];
    int g = bx - 16;                      // 32-row group
    size_t inbase = ((size_t)b*SS + (size_t)g*32)*HID + h*DD;
    float4 vals[4]; float amax = 0.f;
    #pragma unroll
    for (int i = 0; i < 4; i++){
      int f4 = t + i*256;
      int row = f4 >> 5, c4 = f4 & 31;
      float4 x = *(const float4*)(q + inbase + (size_t)row*HID + c4*4);
      vals[i] = x;
      amax = fmaxf(amax, fmaxf(fmaxf(fabsf(x.x), fabsf(x.y)), fmaxf(fabsf(x.z), fabsf(x.w))));
    }
    amax = block_absmax(amax, red);
    float scale = fmaxf(amax / 127.0f, 1e-8f);
    size_t obase = ((size_t)bh*SS + (size_t)g*32)*DD;
    #pragma unroll
    for (int i = 0; i < 4; i++){
      int f4 = t + i*256;
      int row = f4 >> 5, c4 = f4 & 31;
      char4 o;
      o.x = (signed char)(int)fminf(fmaxf(rintf(vals[i].x / scale), -127.f), 127.f);
      o.y = (signed char)(int)fminf(fmaxf(rintf(vals[i].y / scale), -127.f), 127.f);
      o.z = (signed char)(int)fminf(fmaxf(rintf(vals[i].z / scale), -127.f), 127.f);
      o.w = (signed char)(int)fminf(fmaxf(rintf(vals[i].w / scale), -127.f), 127.f);
      *(char4*)(g_q8 + obase + (size_t)row*DD + c4*4) = o;
    }
    if (t == 0) g_qscale[bh*64 + g] = scale;
  }
}

// ---------------- K1: finalize means ----------------
__global__ void __launch_bounds__(128) pre_k1(){
  int bh = blockIdx.x, t = threadIdx.x;
  float ka = 0.f, va = 0.f;
  #pragma unroll
  for (int c = 0; c < 32; c++){
    ka += g_kpart[(bh*32 + c)*DD + t];
    va += g_vpart[(bh*32 + c)*DD + t];
  }
  g_kmean[bh*DD + t] = ka / (float)SS;
  g_vmean[bh*DD + t] = va / (float)SS;
}

// ---------------- K2: quant_k (bx<32) + smooth_v (bx>=32) ----------------
__global__ void __launch_bounds__(256)
pre_k2(const float* __restrict__ k, const float* __restrict__ v){
  int bh = blockIdx.y, bx = blockIdx.x;
  int b = bh >> 4, h = bh & 15;
  int t = threadIdx.x;
  if (bx < 32){
    __shared__ float red[8];
    int g = bx;                           // 64-row group
    size_t inbase = ((size_t)b*SS + (size_t)g*64)*HID + h*DD;
    const float* km = g_kmean + bh*DD;
    float4 vals[8]; float amax = 0.f;
    #pragma unroll
    for (int i = 0; i < 8; i++){
      int f4 = t + i*256;
      int row = f4 >> 5, c4 = f4 & 31;
      float4 x = *(const float4*)(k + inbase + (size_t)row*HID + c4*4);
      x.x -= km[c4*4]; x.y -= km[c4*4+1]; x.z -= km[c4*4+2]; x.w -= km[c4*4+3];
      vals[i] = x;
      amax = fmaxf(amax, fmaxf(fmaxf(fabsf(x.x), fabsf(x.y)), fmaxf(fabsf(x.z), fabsf(x.w))));
    }
    amax = block_absmax(amax, red);
    float scale = fmaxf(amax / 127.0f, 1e-8f);
    size_t obase = ((size_t)bh*SS + (size_t)g*64)*DD;
    #pragma unroll
    for (int i = 0; i < 8; i++){
      int f4 = t + i*256;
      int row = f4 >> 5, c4 = f4 & 31;
      char4 o;
      o.x = (signed char)(int)fminf(fmaxf(rintf(vals[i].x / scale), -127.f), 127.f);
      o.y = (signed char)(int)fminf(fmaxf(rintf(vals[i].y / scale), -127.f), 127.f);
      o.z = (signed char)(int)fminf(fmaxf(rintf(vals[i].z / scale), -127.f), 127.f);
      o.w = (signed char)(int)fminf(fmaxf(rintf(vals[i].w / scale), -127.f), 127.f);
      *(char4*)(g_k8 + obase + (size_t)row*DD + c4*4) = o;
    }
    if (t == 0) g_kscale[bh*32 + g] = scale;
  } else {
    int g = bx - 32;                      // 64 rows of V
    const float* vm = g_vmean + bh*DD;
    size_t inbase = ((size_t)b*SS + (size_t)g*64)*HID + h*DD;
    size_t obase  = ((size_t)bh*SS + (size_t)g*64)*DD;
    #pragma unroll
    for (int i = 0; i < 8; i++){
      int f4 = t + i*256;
      int row = f4 >> 5, c4 = f4 & 31;
      float4 x = *(const float4*)(v + inbase + (size_t)row*HID + c4*4);
      __half2 h0 = __floats2half2_rn(x.x - vm[c4*4],   x.y - vm[c4*4+1]);
      __half2 h1 = __floats2half2_rn(x.z - vm[c4*4+2], x.w - vm[c4*4+3]);
      uint2 o; o.x = *(uint32_t*)&h0; o.y = *(uint32_t*)&h1;
      *(uint2*)(g_v16 + obase + (size_t)row*DD + c4*4) = o;
    }
  }
}

// ---------------- MMA helpers ----------------
__device__ __forceinline__ void mma16816(float c[4], const uint32_t a[4], uint32_t b0, uint32_t b1){
  asm volatile(
    "mma.sync.aligned.m16n8k16.row.col.f32.f16.f16.f32 "
    "{%0,%1,%2,%3}, {%4,%5,%6,%7}, {%8,%9}, {%0,%1,%2,%3};\n"
    : "+f"(c[0]), "+f"(c[1]), "+f"(c[2]), "+f"(c[3])
    : "r"(a[0]), "r"(a[1]), "r"(a[2]), "r"(a[3]), "r"(b0), "r"(b1));
}
__device__ __forceinline__ void mma_s8(int c[4], const uint32_t a[4], uint32_t b0, uint32_t b1){
  asm volatile(
    "mma.sync.aligned.m16n8k32.row.col.s32.s8.s8.s32 "
    "{%0,%1,%2,%3}, {%4,%5,%6,%7}, {%8,%9}, {%0,%1,%2,%3};\n"
    : "+r"(c[0]), "+r"(c[1]), "+r"(c[2]), "+r"(c[3])
    : "r"(a[0]), "r"(a[1]), "r"(a[2]), "r"(a[3]), "r"(b0), "r"(b1));
}
__device__ __forceinline__ void ldmx4t(uint32_t& t0, uint32_t& t1, uint32_t& t2, uint32_t& t3, uint32_t addr){
  asm volatile("ldmatrix.sync.aligned.m8n8.x4.trans.shared.b16 {%0,%1,%2,%3}, [%4];\n"
    : "=r"(t0), "=r"(t1), "=r"(t2), "=r"(t3) : "r"(addr));
}
#define CP16(dst, src) asm volatile("cp.async.cg.shared.global [%0], [%1], 16;\n" :: "r"(dst), "l"(src) : "memory")

#define KPITCH 144
#define VPITCH 272
#define SK_OFF(st) ((st)*64*KPITCH)
#define SV_OFF(st) (2*64*KPITCH + (st)*64*VPITCH)
#define SMEM_TOTAL (2*64*KPITCH + 2*64*VPITCH)   // 53248

// ---------------- main attention kernel ----------------
__global__ void __launch_bounds__(128, 3)
attn_kernel(const int* __restrict__ wlp, const int* __restrict__ wrp, float* __restrict__ out){
  extern __shared__ char smem[];
  const uint32_t smem_b = (uint32_t)__cvta_generic_to_shared(smem);

  const int i0  = blockIdx.x * 64;
  const int bh  = blockIdx.y;
  const int b   = bh >> 4, h = bh & 15;
  const int tid = threadIdx.x, wid = tid >> 5, lane = tid & 31;
  const int r   = lane >> 2, q2 = (lane & 3) * 2, c4 = (lane & 3) * 4;
  const int wl = *wlp, wr = *wrp;

  const signed char* Qg = g_q8 + ((size_t)bh*SS + i0)*DD;
  const signed char* Kg = g_k8 + (size_t)bh*SS*DD;
  const __half*      Vg = g_v16 + (size_t)bh*SS*DD;

  // --- stage Q into stage-0 K region, build int8 A-fragments ---
  {
    char* sQ = smem;
    #pragma unroll
    for (int it = tid; it < 512; it += 128){
      int row = it >> 3, seg = it & 7;
      *(uint4*)(sQ + row*KPITCH + seg*16) = *(const uint4*)(Qg + row*128 + seg*16);
    }
  }
  __syncthreads();
  const int qrow = wid*16 + r;
  uint32_t afrag[4][4];
  #pragma unroll
  for (int kc = 0; kc < 4; kc++){
    const char* sQ = smem;
    afrag[kc][0] = *(const uint32_t*)(sQ + (qrow  )*KPITCH + kc*32 + c4     );
    afrag[kc][1] = *(const uint32_t*)(sQ + (qrow+8)*KPITCH + kc*32 + c4     );
    afrag[kc][2] = *(const uint32_t*)(sQ + (qrow  )*KPITCH + kc*32 + c4 + 16);
    afrag[kc][3] = *(const uint32_t*)(sQ + (qrow+8)*KPITCH + kc*32 + c4 + 16);
  }
  __syncthreads();

  const float qsl = g_qscale[bh*(SS/32) + ((i0 + wid*16) >> 5)] * SM_SCALE_L2E;
  const int i_r0 = i0 + qrow, i_r1 = i_r0 + 8;
  const int lo0 = (wl < 0) ? -0x40000000 : i_r0 - wl;
  const int hi0 = (wr < 0) ?  0x40000000 : i_r0 + wr;
  const int lo1 = (wl < 0) ? -0x40000000 : i_r1 - wl;
  const int hi1 = (wr < 0) ?  0x40000000 : i_r1 + wr;

  float of[16][4];
  #pragma unroll
  for (int n = 0; n < 16; n++){ of[n][0]=0.f; of[n][1]=0.f; of[n][2]=0.f; of[n][3]=0.f; }
  float m0 = -1e30f, m1 = -1e30f, l0 = 0.f, l1 = 0.f;

  int jlo = (wl >= 0) ? max(0, i0 - wl) : 0;
  int jhi = (wr >= 0) ? min(SS-1, i0 + 63 + wr) : SS-1;
  const int jloT = jlo & ~63;
  const int nt = ((jhi - jloT) >> 6) + 1;

  auto issue = [&](int st, int j0){
    uint32_t kb = smem_b + SK_OFF(st);
    const signed char* kg = Kg + (size_t)j0*128;
    #pragma unroll
    for (int c = tid; c < 512; c += 128){
      int row = c >> 3, seg = c & 7;
      CP16(kb + row*KPITCH + seg*16, kg + row*128 + seg*16);
    }
    uint32_t vb = smem_b + SV_OFF(st);
    const __half* vg = Vg + (size_t)j0*128;
    #pragma unroll
    for (int c = tid; c < 1024; c += 128){
      int row = c >> 4, seg = c & 15;
      CP16(vb + row*VPITCH + seg*16, (const char*)vg + row*256 + seg*16);
    }
    asm volatile("cp.async.commit_group;\n" ::: "memory");
  };

  issue(0, jloT);

  for (int it = 0; it < nt; it++){
    const int j0 = jloT + it*64;
    const int st = it & 1;
    if (it + 1 < nt){
      issue(st ^ 1, j0 + 64);
      asm volatile("cp.async.wait_group 1;\n" ::: "memory");
    } else {
      asm volatile("cp.async.wait_group 0;\n" ::: "memory");
    }
    __syncthreads();

    // --- S = Q K^T (int8 MMA, exact) ---
    int acc[8][4];
    #pragma unroll
    for (int n = 0; n < 8; n++){ acc[n][0]=0; acc[n][1]=0; acc[n][2]=0; acc[n][3]=0; }
    const char* sK = smem + SK_OFF(st);
    #pragma unroll
    for (int kc = 0; kc < 4; kc++){
      #pragma unroll
      for (int nf = 0; nf < 8; nf++){
        uint32_t b0 = *(const uint32_t*)(sK + (nf*8 + r)*KPITCH + kc*32 + c4     );
        uint32_t b1 = *(const uint32_t*)(sK + (nf*8 + r)*KPITCH + kc*32 + c4 + 16);
        mma_s8(acc[nf], afrag[kc], b0, b1);
      }
    }

    // --- dequant (base-2 domain) + mask; fast path for interior tiles ---
    const float dq = qsl * g_kscale[bh*(SS/64) + (j0 >> 6)];
    float sf[8][4];
    float mt0 = -INFINITY, mt1 = -INFINITY;
    const bool full = ((wl < 0) || (j0 >= i0 + 63 - wl)) && ((wr < 0) || (j0 + 63 <= i0 + wr));
    if (full){
      #pragma unroll
      for (int nf = 0; nf < 8; nf++){
        float s00 = __int2float_rn(acc[nf][0]) * dq;
        float s01 = __int2float_rn(acc[nf][1]) * dq;
        float s10 = __int2float_rn(acc[nf][2]) * dq;
        float s11 = __int2float_rn(acc[nf][3]) * dq;
        sf[nf][0]=s00; sf[nf][1]=s01; sf[nf][2]=s10; sf[nf][3]=s11;
        mt0 = fmaxf(mt0, fmaxf(s00, s01));
        mt1 = fmaxf(mt1, fmaxf(s10, s11));
      }
    } else {
      #pragma unroll
      for (int nf = 0; nf < 8; nf++){
        int jc = j0 + nf*8 + q2;
        float s00 = (jc   >= lo0 && jc   <= hi0) ? __int2float_rn(acc[nf][0]) * dq : -INFINITY;
        float s01 = (jc+1 >= lo0 && jc+1 <= hi0) ? __int2float_rn(acc[nf][1]) * dq : -INFINITY;
        float s10 = (jc   >= lo1 && jc   <= hi1) ? __int2float_rn(acc[nf][2]) * dq : -INFINITY;
        float s11 = (jc+1 >= lo1 && jc+1 <= hi1) ? __int2float_rn(acc[nf][3]) * dq : -INFINITY;
        sf[nf][0]=s00; sf[nf][1]=s01; sf[nf][2]=s10; sf[nf][3]=s11;
        mt0 = fmaxf(mt0, fmaxf(s00, s01));
        mt1 = fmaxf(mt1, fmaxf(s10, s11));
      }
    }
    mt0 = fmaxf(mt0, __shfl_xor_sync(0xffffffffu, mt0, 1));
    mt0 = fmaxf(mt0, __shfl_xor_sync(0xffffffffu, mt0, 2));
    mt1 = fmaxf(mt1, __shfl_xor_sync(0xffffffffu, mt1, 1));
    mt1 = fmaxf(mt1, __shfl_xor_sync(0xffffffffu, mt1, 2));

    float mn0 = fmaxf(m0, mt0), mn1 = fmaxf(m1, mt1);
    float a0 = exp2f(m0 - mn0), a1 = exp2f(m1 - mn1);
    float t0 = 0.f, t1 = 0.f;
    #pragma unroll
    for (int nf = 0; nf < 8; nf++){
      float e00 = exp2f(sf[nf][0] - mn0);
      float e01 = exp2f(sf[nf][1] - mn0);
      float e10 = exp2f(sf[nf][2] - mn1);
      float e11 = exp2f(sf[nf][3] - mn1);
      sf[nf][0]=e00; sf[nf][1]=e01; sf[nf][2]=e10; sf[nf][3]=e11;
      t0 += e00 + e01; t1 += e10 + e11;
    }
    t0 += __shfl_xor_sync(0xffffffffu, t0, 1);
    t0 += __shfl_xor_sync(0xffffffffu, t0, 2);
    t1 += __shfl_xor_sync(0xffffffffu, t1, 1);
    t1 += __shfl_xor_sync(0xffffffffu, t1, 2);
    l0 = l0*a0 + t0; l1 = l1*a1 + t1;
    m0 = mn0; m1 = mn1;
    #pragma unroll
    for (int n = 0; n < 16; n++){
      of[n][0]*=a0; of[n][1]*=a0; of[n][2]*=a1; of[n][3]*=a1;
    }

    // --- pack P to f16 A-fragments ---
    uint32_t pfrag[4][4];
    #pragma unroll
    for (int kc = 0; kc < 4; kc++){
      __half2 p0 = __floats2half2_rn(sf[2*kc  ][0], sf[2*kc  ][1]);
      __half2 p1 = __floats2half2_rn(sf[2*kc  ][2], sf[2*kc  ][3]);
      __half2 p2 = __floats2half2_rn(sf[2*kc+1][0], sf[2*kc+1][1]);
      __half2 p3 = __floats2half2_rn(sf[2*kc+1][2], sf[2*kc+1][3]);
      pfrag[kc][0] = *(uint32_t*)&p0; pfrag[kc][1] = *(uint32_t*)&p1;
      pfrag[kc][2] = *(uint32_t*)&p2; pfrag[kc][3] = *(uint32_t*)&p3;
    }

    // --- O += P V : V^T fragments via ldmatrix.trans ---
    const uint32_t svb = smem_b + SV_OFF(st);
    const int jrow = lane & 15;
    const int dsel = (lane & 16) ? 8 : 0;
    #pragma unroll
    for (int jc = 0; jc < 4; jc++){
      #pragma unroll
      for (int dc = 0; dc < 8; dc++){
        uint32_t addr = svb + (jc*16 + jrow)*VPITCH + (dc*16 + dsel)*2;
        uint32_t v0, v1, v2, v3;
        ldmx4t(v0, v1, v2, v3, addr);
        mma16816(of[dc*2    ], pfrag[jc], v0, v1);
        mma16816(of[dc*2 + 1], pfrag[jc], v2, v3);
      }
    }
    __syncthreads();
  }

  // --- epilogue: normalize, f16-round, add v_mean ---
  float inv0 = 1.0f / l0, inv1 = 1.0f / l1;
  float* ob = out + ((size_t)b*SS)*HID + h*DD;
  const float* vm = g_vmean + bh*DD;
  #pragma unroll
  for (int n = 0; n < 16; n++){
    int d0 = n*8 + q2;
    float2 o0, o1;
    o0.x = __half2float(__float2half_rn(of[n][0]*inv0)) + vm[d0];
    o0.y = __half2float(__float2half_rn(of[n][1]*inv0)) + vm[d0+1];
    o1.x = __half2float(__float2half_rn(of[n][2]*inv1)) + vm[d0];
    o1.y = __half2float(__float2half_rn(of[n][3]*inv1)) + vm[d0+1];
    *(float2*)(ob + (size_t)i_r0*HID + d0) = o0;
    *(float2*)(ob + (size_t)i_r1*HID + d0) = o1;
  }
}

// ---------------- launch ----------------
extern "C" void kernel_launch(void* const* d_in, const int* in_sizes, int n_in,
                              void* d_out, int out_size){
  const float* q = (const float*)d_in[0];
  const float* k = (const float*)d_in[1];
  const float* v = (const float*)d_in[2];
  const int* wl  = (const int*)d_in[3];
  const int* wr  = (const int*)d_in[4];
  float* out = (float*)d_out;

  cudaFuncSetAttribute(attn_kernel, cudaFuncAttributeMaxDynamicSharedMemorySize, SMEM_TOTAL);

  pre_k0<<<dim3(80, BB*HH), 256>>>(q, k, v);
  pre_k1<<<BB*HH, 128>>>();
  pre_k2<<<dim3(64, BB*HH), 256>>>(k, v);
  attn_kernel<<<dim3(SS/64, BB*HH), 128, SMEM_TOTAL>>>(wl, wr, out);
}

// round 4
// speedup vs baseline: 2.0561x; 1.0858x over previous
#include <cuda_runtime.h>
#include <cuda_fp16.h>
#include <math.h>
#include <stdint.h>

#define BB 2
#define SS 2048
#define HH 16
#define DD 128
#define HID (HH*DD)
#define SM_SCALE_L2E 0.12751649736230442f   /* (1/sqrt(128)) * log2(e) */

// ---------------- scratch (no allocation allowed) ----------------
__device__ signed char g_q8[(size_t)BB*HH*SS*DD];
__device__ signed char g_k8[(size_t)BB*HH*SS*DD];
__device__ __half      g_v16[(size_t)BB*HH*SS*DD];
__device__ float g_qscale[BB*HH*(SS/32)];
__device__ float g_kscale[BB*HH*(SS/64)];
__device__ float g_vmean[BB*HH*DD];
__device__ float g_kpart[BB*HH*32*DD];
__device__ float g_vpart[BB*HH*32*DD];

// ---------------- block absmax (256 threads / 8 warps) ----------------
__device__ __forceinline__ float block_absmax(float v, float* red){
  #pragma unroll
  for (int o = 16; o > 0; o >>= 1)
    v = fmaxf(v, __shfl_xor_sync(0xffffffffu, v, o));
  int w = threadIdx.x >> 5;
  if ((threadIdx.x & 31) == 0) red[w] = v;
  __syncthreads();
  float r = red[0];
  #pragma unroll
  for (int i = 1; i < 8; i++) r = fmaxf(r, red[i]);
  return r;
}

// ---------------- K0: mean partials (bx<16) + quant_q (bx>=16) ----------------
__global__ void __launch_bounds__(256)
pre_k0(const float* __restrict__ q, const float* __restrict__ k, const float* __restrict__ v){
  int bh = blockIdx.y, bx = blockIdx.x;
  int b = bh >> 4, h = bh & 15;
  int t = threadIdx.x;
  if (bx < 16){
    int d = t & 127, hf = t >> 7;
    size_t base = ((size_t)b*SS + (size_t)bx*128 + (size_t)hf*64)*HID + h*DD + d;
    float ka = 0.f, va = 0.f;
    #pragma unroll 4
    for (int r2 = 0; r2 < 64; r2++){
      ka += k[base + (size_t)r2*HID];
      va += v[base + (size_t)r2*HID];
    }
    g_kpart[((bh*16 + bx)*2 + hf)*DD + d] = ka;
    g_vpart[((bh*16 + bx)*2 + hf)*DD + d] = va;
  } else {
    __shared__ float red[8];
    int g = bx - 16;                      // 32-row group
    size_t inbase = ((size_t)b*SS + (size_t)g*32)*HID + h*DD;
    float4 vals[4]; float amax = 0.f;
    #pragma unroll
    for (int i = 0; i < 4; i++){
      int f4 = t + i*256;
      int row = f4 >> 5, c4 = f4 & 31;
      float4 x = *(const float4*)(q + inbase + (size_t)row*HID + c4*4);
      vals[i] = x;
      amax = fmaxf(amax, fmaxf(fmaxf(fabsf(x.x), fabsf(x.y)), fmaxf(fabsf(x.z), fabsf(x.w))));
    }
    amax = block_absmax(amax, red);
    float scale = fmaxf(amax / 127.0f, 1e-8f);
    size_t obase = ((size_t)bh*SS + (size_t)g*32)*DD;
    #pragma unroll
    for (int i = 0; i < 4; i++){
      int f4 = t + i*256;
      int row = f4 >> 5, c4 = f4 & 31;
      char4 o;
      o.x = (signed char)(int)fminf(fmaxf(rintf(vals[i].x / scale), -127.f), 127.f);
      o.y = (signed char)(int)fminf(fmaxf(rintf(vals[i].y / scale), -127.f), 127.f);
      o.z = (signed char)(int)fminf(fmaxf(rintf(vals[i].z / scale), -127.f), 127.f);
      o.w = (signed char)(int)fminf(fmaxf(rintf(vals[i].w / scale), -127.f), 127.f);
      *(char4*)(g_q8 + obase + (size_t)row*DD + c4*4) = o;
    }
    if (t == 0) g_qscale[bh*64 + g] = scale;
  }
}

// ---------------- K1: quant_k (bx<32) + smooth_v (bx>=32); means computed in-block ----------------
__global__ void __launch_bounds__(256)
pre_k2(const float* __restrict__ k, const float* __restrict__ v){
  __shared__ float smean[128];
  int bh = blockIdx.y, bx = blockIdx.x;
  int b = bh >> 4, h = bh & 15;
  int t = threadIdx.x;
  // means from partials (redundant per block, tiny; L2 hits)
  if (t < 128){
    const float* part = (bx < 32) ? g_kpart : g_vpart;
    float a = 0.f;
    #pragma unroll
    for (int c = 0; c < 32; c++) a += part[(bh*32 + c)*DD + t];
    smean[t] = a / (float)SS;
    if (bx >= 32) g_vmean[bh*DD + t] = smean[t];   // attn epilogue needs v_mean
  }
  __syncthreads();
  if (bx < 32){
    __shared__ float red[8];
    int g = bx;                           // 64-row group
    size_t inbase = ((size_t)b*SS + (size_t)g*64)*HID + h*DD;
    float4 vals[8]; float amax = 0.f;
    #pragma unroll
    for (int i = 0; i < 8; i++){
      int f4 = t + i*256;
      int row = f4 >> 5, c4 = f4 & 31;
      float4 x = *(const float4*)(k + inbase + (size_t)row*HID + c4*4);
      x.x -= smean[c4*4]; x.y -= smean[c4*4+1]; x.z -= smean[c4*4+2]; x.w -= smean[c4*4+3];
      vals[i] = x;
      amax = fmaxf(amax, fmaxf(fmaxf(fabsf(x.x), fabsf(x.y)), fmaxf(fabsf(x.z), fabsf(x.w))));
    }
    amax = block_absmax(amax, red);
    float scale = fmaxf(amax / 127.0f, 1e-8f);
    size_t obase = ((size_t)bh*SS + (size_t)g*64)*DD;
    #pragma unroll
    for (int i = 0; i < 8; i++){
      int f4 = t + i*256;
      int row = f4 >> 5, c4 = f4 & 31;
      char4 o;
      o.x = (signed char)(int)fminf(fmaxf(rintf(vals[i].x / scale), -127.f), 127.f);
      o.y = (signed char)(int)fminf(fmaxf(rintf(vals[i].y / scale), -127.f), 127.f);
      o.z = (signed char)(int)fminf(fmaxf(rintf(vals[i].z / scale), -127.f), 127.f);
      o.w = (signed char)(int)fminf(fmaxf(rintf(vals[i].w / scale), -127.f), 127.f);
      *(char4*)(g_k8 + obase + (size_t)row*DD + c4*4) = o;
    }
    if (t == 0) g_kscale[bh*32 + g] = scale;
  } else {
    int g = bx - 32;                      // 64 rows of V
    size_t inbase = ((size_t)b*SS + (size_t)g*64)*HID + h*DD;
    size_t obase  = ((size_t)bh*SS + (size_t)g*64)*DD;
    #pragma unroll
    for (int i = 0; i < 8; i++){
      int f4 = t + i*256;
      int row = f4 >> 5, c4 = f4 & 31;
      float4 x = *(const float4*)(v + inbase + (size_t)row*HID + c4*4);
      __half2 h0 = __floats2half2_rn(x.x - smean[c4*4],   x.y - smean[c4*4+1]);
      __half2 h1 = __floats2half2_rn(x.z - smean[c4*4+2], x.w - smean[c4*4+3]);
      uint2 o; o.x = *(uint32_t*)&h0; o.y = *(uint32_t*)&h1;
      *(uint2*)(g_v16 + obase + (size_t)row*DD + c4*4) = o;
    }
  }
}

// ---------------- MMA helpers ----------------
__device__ __forceinline__ void mma16816(float c[4], const uint32_t a[4], uint32_t b0, uint32_t b1){
  asm volatile(
    "mma.sync.aligned.m16n8k16.row.col.f32.f16.f16.f32 "
    "{%0,%1,%2,%3}, {%4,%5,%6,%7}, {%8,%9}, {%0,%1,%2,%3};\n"
    : "+f"(c[0]), "+f"(c[1]), "+f"(c[2]), "+f"(c[3])
    : "r"(a[0]), "r"(a[1]), "r"(a[2]), "r"(a[3]), "r"(b0), "r"(b1));
}
__device__ __forceinline__ void mma_s8(int c[4], const uint32_t a[4], uint32_t b0, uint32_t b1){
  asm volatile(
    "mma.sync.aligned.m16n8k32.row.col.s32.s8.s8.s32 "
    "{%0,%1,%2,%3}, {%4,%5,%6,%7}, {%8,%9}, {%0,%1,%2,%3};\n"
    : "+r"(c[0]), "+r"(c[1]), "+r"(c[2]), "+r"(c[3])
    : "r"(a[0]), "r"(a[1]), "r"(a[2]), "r"(a[3]), "r"(b0), "r"(b1));
}
__device__ __forceinline__ void ldmx4(uint32_t& t0, uint32_t& t1, uint32_t& t2, uint32_t& t3, uint32_t addr){
  asm volatile("ldmatrix.sync.aligned.m8n8.x4.shared.b16 {%0,%1,%2,%3}, [%4];\n"
    : "=r"(t0), "=r"(t1), "=r"(t2), "=r"(t3) : "r"(addr));
}
__device__ __forceinline__ void ldmx4t(uint32_t& t0, uint32_t& t1, uint32_t& t2, uint32_t& t3, uint32_t addr){
  asm volatile("ldmatrix.sync.aligned.m8n8.x4.trans.shared.b16 {%0,%1,%2,%3}, [%4];\n"
    : "=r"(t0), "=r"(t1), "=r"(t2), "=r"(t3) : "r"(addr));
}
#define CP16(dst, src) asm volatile("cp.async.cg.shared.global [%0], [%1], 16;\n" :: "r"(dst), "l"(src) : "memory")

#define KPITCH 144
#define VPITCH 272
#define SK_OFF(st) ((st)*64*KPITCH)
#define SV_OFF(st) (2*64*KPITCH + (st)*64*VPITCH)
#define SMEM_TOTAL (2*64*KPITCH + 2*64*VPITCH)   // 53248

// ---------------- main attention kernel ----------------
__global__ void __launch_bounds__(128, 3)
attn_kernel(const int* __restrict__ wlp, const int* __restrict__ wrp, float* __restrict__ out){
  extern __shared__ char smem[];
  const uint32_t smem_b = (uint32_t)__cvta_generic_to_shared(smem);

  // work-descending q-tile order: interior tiles (max key count) first
  const int bx = blockIdx.x;
  const int xq = (bx & 1) ? (16 + (bx >> 1)) : (15 - (bx >> 1));
  const int i0  = xq * 64;
  const int bh  = blockIdx.y;
  const int b   = bh >> 4, h = bh & 15;
  const int tid = threadIdx.x, wid = tid >> 5, lane = tid & 31;
  const int r   = lane >> 2, q2 = (lane & 3) * 2, c4 = (lane & 3) * 4;
  const int wl = *wlp, wr = *wrp;

  const signed char* Qg = g_q8 + ((size_t)bh*SS + i0)*DD;
  const signed char* Kg = g_k8 + (size_t)bh*SS*DD;
  const __half*      Vg = g_v16 + (size_t)bh*SS*DD;

  // --- stage Q into stage-0 K region, build int8 A-fragments ---
  {
    char* sQ = smem;
    #pragma unroll
    for (int it = tid; it < 512; it += 128){
      int row = it >> 3, seg = it & 7;
      *(uint4*)(sQ + row*KPITCH + seg*16) = *(const uint4*)(Qg + row*128 + seg*16);
    }
  }
  __syncthreads();
  const int qrow = wid*16 + r;
  uint32_t afrag[4][4];
  #pragma unroll
  for (int kc = 0; kc < 4; kc++){
    const char* sQ = smem;
    afrag[kc][0] = *(const uint32_t*)(sQ + (qrow  )*KPITCH + kc*32 + c4     );
    afrag[kc][1] = *(const uint32_t*)(sQ + (qrow+8)*KPITCH + kc*32 + c4     );
    afrag[kc][2] = *(const uint32_t*)(sQ + (qrow  )*KPITCH + kc*32 + c4 + 16);
    afrag[kc][3] = *(const uint32_t*)(sQ + (qrow+8)*KPITCH + kc*32 + c4 + 16);
  }
  __syncthreads();

  const float qsl = g_qscale[bh*(SS/32) + ((i0 + wid*16) >> 5)] * SM_SCALE_L2E;
  const int i_r0 = i0 + qrow, i_r1 = i_r0 + 8;
  const int lo0 = (wl < 0) ? -0x40000000 : i_r0 - wl;
  const int hi0 = (wr < 0) ?  0x40000000 : i_r0 + wr;
  const int lo1 = (wl < 0) ? -0x40000000 : i_r1 - wl;
  const int hi1 = (wr < 0) ?  0x40000000 : i_r1 + wr;

  float of[16][4];
  #pragma unroll
  for (int n = 0; n < 16; n++){ of[n][0]=0.f; of[n][1]=0.f; of[n][2]=0.f; of[n][3]=0.f; }
  float m0 = -1e30f, m1 = -1e30f, l0 = 0.f, l1 = 0.f;  // l: per-lane partials

  int jlo = (wl >= 0) ? max(0, i0 - wl) : 0;
  int jhi = (wr >= 0) ? min(SS-1, i0 + 63 + wr) : SS-1;
  const int jloT = jlo & ~63;
  const int nt = ((jhi - jloT) >> 6) + 1;

  auto issue = [&](int st, int j0){
    uint32_t kb = smem_b + SK_OFF(st);
    const signed char* kg = Kg + (size_t)j0*128;
    #pragma unroll
    for (int c = tid; c < 512; c += 128){
      int row = c >> 3, seg = c & 7;
      CP16(kb + row*KPITCH + seg*16, kg + row*128 + seg*16);
    }
    uint32_t vb = smem_b + SV_OFF(st);
    const __half* vg = Vg + (size_t)j0*128;
    #pragma unroll
    for (int c = tid; c < 1024; c += 128){
      int row = c >> 4, seg = c & 15;
      CP16(vb + row*VPITCH + seg*16, (const char*)vg + row*256 + seg*16);
    }
    asm volatile("cp.async.commit_group;\n" ::: "memory");
  };

  issue(0, jloT);

  // per-thread ldmatrix row address (within K tile): lane mapping for x4
  const int ldm_g = lane >> 3;
  const uint32_t kfrag_off = (uint32_t)(((ldm_g >> 1)*8 + (lane & 7))*KPITCH + (ldm_g & 1)*16);

  for (int it = 0; it < nt; it++){
    const int j0 = jloT + it*64;
    const int st = it & 1;
    if (it + 1 < nt){
      issue(st ^ 1, j0 + 64);
      asm volatile("cp.async.wait_group 1;\n" ::: "memory");
    } else {
      asm volatile("cp.async.wait_group 0;\n" ::: "memory");
    }
    __syncthreads();

    // --- S = Q K^T (int8 MMA, exact); B-frags via ldmatrix.x4 ---
    int acc[8][4];
    #pragma unroll
    for (int n = 0; n < 8; n++){ acc[n][0]=0; acc[n][1]=0; acc[n][2]=0; acc[n][3]=0; }
    const uint32_t kfb = smem_b + SK_OFF(st) + kfrag_off;
    #pragma unroll
    for (int m = 0; m < 16; m++){
      const int kc = m >> 2, nfp = m & 3;
      uint32_t b0, b1, b2, b3;
      ldmx4(b0, b1, b2, b3, kfb + nfp*(16*KPITCH) + kc*32);
      mma_s8(acc[nfp*2    ], afrag[kc], b0, b1);
      mma_s8(acc[nfp*2 + 1], afrag[kc], b2, b3);
    }

    // --- dequant (base-2 domain) + mask; fast path for interior tiles ---
    const float dq = qsl * g_kscale[bh*(SS/64) + (j0 >> 6)];
    float sf[8][4];
    float mt0 = -INFINITY, mt1 = -INFINITY;
    const bool full = ((wl < 0) || (j0 >= i0 + 63 - wl)) && ((wr < 0) || (j0 + 63 <= i0 + wr));
    if (full){
      #pragma unroll
      for (int nf = 0; nf < 8; nf++){
        float s00 = __int2float_rn(acc[nf][0]) * dq;
        float s01 = __int2float_rn(acc[nf][1]) * dq;
        float s10 = __int2float_rn(acc[nf][2]) * dq;
        float s11 = __int2float_rn(acc[nf][3]) * dq;
        sf[nf][0]=s00; sf[nf][1]=s01; sf[nf][2]=s10; sf[nf][3]=s11;
        mt0 = fmaxf(mt0, fmaxf(s00, s01));
        mt1 = fmaxf(mt1, fmaxf(s10, s11));
      }
    } else {
      #pragma unroll
      for (int nf = 0; nf < 8; nf++){
        int jc = j0 + nf*8 + q2;
        float s00 = (jc   >= lo0 && jc   <= hi0) ? __int2float_rn(acc[nf][0]) * dq : -INFINITY;
        float s01 = (jc+1 >= lo0 && jc+1 <= hi0) ? __int2float_rn(acc[nf][1]) * dq : -INFINITY;
        float s10 = (jc   >= lo1 && jc   <= hi1) ? __int2float_rn(acc[nf][2]) * dq : -INFINITY;
        float s11 = (jc+1 >= lo1 && jc+1 <= hi1) ? __int2float_rn(acc[nf][3]) * dq : -INFINITY;
        sf[nf][0]=s00; sf[nf][1]=s01; sf[nf][2]=s10; sf[nf][3]=s11;
        mt0 = fmaxf(mt0, fmaxf(s00, s01));
        mt1 = fmaxf(mt1, fmaxf(s10, s11));
      }
    }
    mt0 = fmaxf(mt0, __shfl_xor_sync(0xffffffffu, mt0, 1));
    mt0 = fmaxf(mt0, __shfl_xor_sync(0xffffffffu, mt0, 2));
    mt1 = fmaxf(mt1, __shfl_xor_sync(0xffffffffu, mt1, 1));
    mt1 = fmaxf(mt1, __shfl_xor_sync(0xffffffffu, mt1, 2));

    const bool raise = (mt0 > m0) || (mt1 > m1);
    float mn0 = fmaxf(m0, mt0), mn1 = fmaxf(m1, mt1);
    float a0 = exp2f(m0 - mn0), a1 = exp2f(m1 - mn1);
    float t0 = 0.f, t1 = 0.f;
    #pragma unroll
    for (int nf = 0; nf < 8; nf++){
      float e00 = exp2f(sf[nf][0] - mn0);
      float e01 = exp2f(sf[nf][1] - mn0);
      float e10 = exp2f(sf[nf][2] - mn1);
      float e11 = exp2f(sf[nf][3] - mn1);
      sf[nf][0]=e00; sf[nf][1]=e01; sf[nf][2]=e10; sf[nf][3]=e11;
      t0 += e00 + e01; t1 += e10 + e11;
    }
    l0 = l0*a0 + t0; l1 = l1*a1 + t1;   // per-lane partials (quad-uniform a)
    m0 = mn0; m1 = mn1;
    if (__ballot_sync(0xffffffffu, raise)){
      #pragma unroll
      for (int n = 0; n < 16; n++){
        of[n][0]*=a0; of[n][1]*=a0; of[n][2]*=a1; of[n][3]*=a1;
      }
    }

    // --- pack P to f16 A-fragments ---
    uint32_t pfrag[4][4];
    #pragma unroll
    for (int kc = 0; kc < 4; kc++){
      __half2 p0 = __floats2half2_rn(sf[2*kc  ][0], sf[2*kc  ][1]);
      __half2 p1 = __floats2half2_rn(sf[2*kc  ][2], sf[2*kc  ][3]);
      __half2 p2 = __floats2half2_rn(sf[2*kc+1][0], sf[2*kc+1][1]);
      __half2 p3 = __floats2half2_rn(sf[2*kc+1][2], sf[2*kc+1][3]);
      pfrag[kc][0] = *(uint32_t*)&p0; pfrag[kc][1] = *(uint32_t*)&p1;
      pfrag[kc][2] = *(uint32_t*)&p2; pfrag[kc][3] = *(uint32_t*)&p3;
    }

    // --- O += P V : V^T fragments via ldmatrix.trans ---
    const uint32_t svb = smem_b + SV_OFF(st);
    const int jrow = lane & 15;
    const int dsel = (lane & 16) ? 8 : 0;
    #pragma unroll
    for (int jc = 0; jc < 4; jc++){
      #pragma unroll
      for (int dc = 0; dc < 8; dc++){
        uint32_t addr = svb + (jc*16 + jrow)*VPITCH + (dc*16 + dsel)*2;
        uint32_t v0, v1, v2, v3;
        ldmx4t(v0, v1, v2, v3, addr);
        mma16816(of[dc*2    ], pfrag[jc], v0, v1);
        mma16816(of[dc*2 + 1], pfrag[jc], v2, v3);
      }
    }
    __syncthreads();
  }

  // --- epilogue: reduce l over quad, normalize, f16-round, add v_mean ---
  l0 += __shfl_xor_sync(0xffffffffu, l0, 1);
  l0 += __shfl_xor_sync(0xffffffffu, l0, 2);
  l1 += __shfl_xor_sync(0xffffffffu, l1, 1);
  l1 += __shfl_xor_sync(0xffffffffu, l1, 2);
  float inv0 = 1.0f / l0, inv1 = 1.0f / l1;
  float* ob = out + ((size_t)b*SS)*HID + h*DD;
  const float* vm = g_vmean + bh*DD;
  #pragma unroll
  for (int n = 0; n < 16; n++){
    int d0 = n*8 + q2;
    float2 o0, o1;
    o0.x = __half2float(__float2half_rn(of[n][0]*inv0)) + vm[d0];
    o0.y = __half2float(__float2half_rn(of[n][1]*inv0)) + vm[d0+1];
    o1.x = __half2float(__float2half_rn(of[n][2]*inv1)) + vm[d0];
    o1.y = __half2float(__float2half_rn(of[n][3]*inv1)) + vm[d0+1];
    *(float2*)(ob + (size_t)i_r0*HID + d0) = o0;
    *(float2*)(ob + (size_t)i_r1*HID + d0) = o1;
  }
}

// ---------------- launch ----------------
extern "C" void kernel_launch(void* const* d_in, const int* in_sizes, int n_in,
                              void* d_out, int out_size){
  const float* q = (const float*)d_in[0];
  const float* k = (const float*)d_in[1];
  const float* v = (const float*)d_in[2];
  const int* wl  = (const int*)d_in[3];
  const int* wr  = (const int*)d_in[4];
  float* out = (float*)d_out;

  cudaFuncSetAttribute(attn_kernel, cudaFuncAttributeMaxDynamicSharedMemorySize, SMEM_TOTAL);

  pre_k0<<<dim3(80, BB*HH), 256>>>(q, k, v);
  pre_k2<<<dim3(64, BB*HH), 256>>>(k, v);
  attn_kernel<<<dim3(SS/64, BB*HH), 128, SMEM_TOTAL>>>(wl, wr, out);
}